// round 2
// baseline (speedup 1.0000x reference)
#include <cuda_runtime.h>
#include <cuda_bf16.h>
#include <cstdint>

// Problem constants (fixed shapes)
#define BATCH 32768
#define DIM   1024
#define NH    8
#define HDIM  128
#define HID   1024
#define KCONV 4
#define EPS_  1e-6f
#define CAP_  15.0f

// ---------------- scratch (static device globals; no allocation) -------------
__device__ float g_xconv[(size_t)BATCH * DIM];   // SiLU(conv gemm)
__device__ float g_z[(size_t)BATCH * DIM];       // z projection
__device__ float g_hnorm[(size_t)BATCH * DIM];   // layer-normed hidden
__device__ float g_w1[(size_t)DIM * DIM];        // packed conv_w[:,:,K-1]

// ---------------- pack conv weight slice ------------------------------------
__global__ void pack_conv_kernel(const float* __restrict__ conv_w) {
    int idx = blockIdx.x * blockDim.x + threadIdx.x;   // over D*D
    if (idx < DIM * DIM) {
        // conv_w layout [out=D][in=D][K]; take tap K-1
        g_w1[idx] = conv_w[(size_t)idx * KCONV + (KCONV - 1)];
    }
}

// ---------------- fp32 tiled NT GEMM: C[m][n] = sum_k A[m][k]*W[n][k] --------
// BM=BN=128, BK=16, 256 threads, 8x8 per thread.
#define BM 128
#define BN 128
#define BK 16
#define TM 8
#define TN 8

template <int ACT>  // 0: none, 1: SiLU
__global__ __launch_bounds__(256, 2)
void gemm_nt_kernel(const float* __restrict__ A, const float* __restrict__ W,
                    const float* __restrict__ bias, float* __restrict__ C,
                    int N, int K) {
    __shared__ float As[BK][BM + 4];
    __shared__ float Bs[BK][BN + 4];

    const int bm = blockIdx.y * BM;
    const int bn = blockIdx.x * BN;
    const int tid = threadIdx.x;
    const int tm = (tid >> 4) * TM;     // 0..120
    const int tn = (tid & 15) * TN;     // 0..120

    float acc[TM][TN];
#pragma unroll
    for (int i = 0; i < TM; i++)
#pragma unroll
        for (int j = 0; j < TN; j++) acc[i][j] = 0.f;

    for (int k0 = 0; k0 < K; k0 += BK) {
        // cooperative load: 128x16 tile = 512 float4; 2 per thread
#pragma unroll
        for (int l = 0; l < 2; l++) {
            int id  = tid + l * 256;
            int row = id >> 2;
            int kq  = (id & 3) * 4;
            float4 a = *(const float4*)(A + (size_t)(bm + row) * K + k0 + kq);
            As[kq + 0][row] = a.x; As[kq + 1][row] = a.y;
            As[kq + 2][row] = a.z; As[kq + 3][row] = a.w;
            float4 b = *(const float4*)(W + (size_t)(bn + row) * K + k0 + kq);
            Bs[kq + 0][row] = b.x; Bs[kq + 1][row] = b.y;
            Bs[kq + 2][row] = b.z; Bs[kq + 3][row] = b.w;
        }
        __syncthreads();

#pragma unroll
        for (int k = 0; k < BK; k++) {
            float ra[TM], rb[TN];
            float4 a0 = *(const float4*)&As[k][tm];
            float4 a1 = *(const float4*)&As[k][tm + 4];
            float4 b0 = *(const float4*)&Bs[k][tn];
            float4 b1 = *(const float4*)&Bs[k][tn + 4];
            ra[0]=a0.x; ra[1]=a0.y; ra[2]=a0.z; ra[3]=a0.w;
            ra[4]=a1.x; ra[5]=a1.y; ra[6]=a1.z; ra[7]=a1.w;
            rb[0]=b0.x; rb[1]=b0.y; rb[2]=b0.z; rb[3]=b0.w;
            rb[4]=b1.x; rb[5]=b1.y; rb[6]=b1.z; rb[7]=b1.w;
#pragma unroll
            for (int i = 0; i < TM; i++)
#pragma unroll
                for (int j = 0; j < TN; j++)
                    acc[i][j] = fmaf(ra[i], rb[j], acc[i][j]);
        }
        __syncthreads();
    }

    // epilogue
#pragma unroll
    for (int i = 0; i < TM; i++) {
        size_t row = (size_t)(bm + tm + i);
        float* crow = C + row * N + bn + tn;
#pragma unroll
        for (int j = 0; j < TN; j += 4) {
            float4 v;
            float vv[4];
#pragma unroll
            for (int q = 0; q < 4; q++) {
                float x = acc[i][j + q];
                if (bias) x += bias[bn + tn + j + q];
                if (ACT == 1) {
                    // SiLU: x * sigmoid(x)
                    x = x / (1.f + __expf(-x));
                }
                vv[q] = x;
            }
            v.x = vv[0]; v.y = vv[1]; v.z = vv[2]; v.w = vv[3];
            *(float4*)(crow + j) = v;
        }
    }
}

// ---------------- gating + per-head layernorm --------------------------------
__device__ __forceinline__ float warp_sum(float v) {
#pragma unroll
    for (int o = 16; o; o >>= 1) v += __shfl_xor_sync(0xffffffffu, v, o);
    return v;
}

__device__ __forceinline__ float softcap(float x) {
    return CAP_ * tanhf(x * (1.0f / CAP_));
}

__global__ __launch_bounds__(256)
void gate_kernel(const float* __restrict__ inputs,
                 const float* __restrict__ c, const float* __restrict__ n,
                 const float* __restrict__ m,
                 const float* __restrict__ i_w, const float* __restrict__ i_b,
                 const float* __restrict__ f_w, const float* __restrict__ f_b,
                 const float* __restrict__ o_w, const float* __restrict__ o_b,
                 const float* __restrict__ gn_w, const float* __restrict__ gn_b,
                 float* __restrict__ out_c, float* __restrict__ out_n,
                 float* __restrict__ out_m) {
    const int b = blockIdx.x;
    const int tid = threadIdx.x;
    const int h = tid >> 5;          // warp == head (NH==8 warps)
    const int lane = tid & 31;

    __shared__ float s_in[DIM];
    __shared__ float s_xc[DIM];

    const float* inrow = inputs + (size_t)b * DIM;
    const float* xcrow = g_xconv + (size_t)b * DIM;
    for (int i = tid; i < DIM; i += 256) {
        s_in[i] = inrow[i];
        s_xc[i] = xcrow[i];
    }
    __syncthreads();

    // gate projections for this head
    const float* iw = i_w + h * DIM;
    const float* fw = f_w + h * DIM;
    const float* ow = o_w + h * DIM;
    float di = 0.f, df = 0.f, dq = 0.f;
#pragma unroll 8
    for (int k = lane; k < DIM; k += 32) {
        float xc = s_xc[k];
        float xi = s_in[k];
        di = fmaf(xc, iw[k], di);
        df = fmaf(xc, fw[k], df);
        dq = fmaf(xi, ow[k], dq);
    }
    di = warp_sum(di);
    df = warp_sum(df);
    dq = warp_sum(dq);

    float i_t = softcap(di + i_b[h]);
    float f_t = softcap(df + f_b[h]);
    float o_t = dq + o_b[h];

    float f_log = -log1pf(expf(-f_t));       // log(sigmoid(f_t)); f_t in [-15,15]
    float mm    = m[(size_t)b * NH + h];
    float m_new = fmaxf(f_log + mm, i_t);
    float i_g   = expf(i_t - m_new);
    float f_g   = expf(f_log + mm - m_new);
    float o_g   = 1.f / (1.f + expf(-o_t));

    const size_t base = (size_t)b * HID + h * HDIM;
    const float* crow = c + base;
    const float* nrow = n + base;
    const float* zrow = g_z + base;

    float hv[4];
    float sum = 0.f, sumsq = 0.f;
#pragma unroll
    for (int jj = 0; jj < 4; jj++) {
        int idx = lane + jj * 32;
        float cn = fmaf(f_g, crow[idx], i_g * zrow[idx]);
        float nn = fmaf(f_g, nrow[idx], i_g);
        out_c[base + idx] = cn;
        out_n[base + idx] = nn;
        float hh = o_g * cn / (nn + EPS_);
        hv[jj] = hh;
        sum += hh;
        sumsq = fmaf(hh, hh, sumsq);
    }
    sum   = warp_sum(sum);
    sumsq = warp_sum(sumsq);
    float mu   = sum * (1.0f / HDIM);
    float var  = sumsq * (1.0f / HDIM) - mu * mu;
    float rstd = rsqrtf(var + EPS_);
#pragma unroll
    for (int jj = 0; jj < 4; jj++) {
        int idx = lane + jj * 32;
        float hn = (hv[jj] - mu) * rstd * gn_w[h * HDIM + idx] + gn_b[h * HDIM + idx];
        g_hnorm[base + idx] = hn;
    }
    if (lane == 0) out_m[(size_t)b * NH + h] = m_new;
}

// ---------------- launch ------------------------------------------------------
extern "C" void kernel_launch(void* const* d_in, const int* in_sizes, int n_in,
                              void* d_out, int out_size) {
    const float* inputs = (const float*)d_in[0];
    const float* c      = (const float*)d_in[1];
    const float* n      = (const float*)d_in[2];
    const float* m      = (const float*)d_in[3];
    const float* conv_w = (const float*)d_in[4];
    const float* conv_b = (const float*)d_in[5];
    const float* z_w    = (const float*)d_in[6];
    const float* i_w    = (const float*)d_in[7];
    const float* i_b    = (const float*)d_in[8];
    const float* f_w    = (const float*)d_in[9];
    const float* f_b    = (const float*)d_in[10];
    const float* o_w    = (const float*)d_in[11];
    const float* o_b    = (const float*)d_in[12];
    const float* gn_w   = (const float*)d_in[13];
    const float* gn_b   = (const float*)d_in[14];
    const float* out_w  = (const float*)d_in[15];

    float* out   = (float*)d_out;                       // [B, D]
    float* out_c = out   + (size_t)BATCH * DIM;         // [B, NH, H]
    float* out_n = out_c + (size_t)BATCH * DIM;         // [B, NH, H]
    float* out_m = out_n + (size_t)BATCH * DIM;         // [B, NH]

    float *xconv_p, *z_p, *hnorm_p, *w1_p;
    cudaGetSymbolAddress((void**)&xconv_p, g_xconv);
    cudaGetSymbolAddress((void**)&z_p, g_z);
    cudaGetSymbolAddress((void**)&hnorm_p, g_hnorm);
    cudaGetSymbolAddress((void**)&w1_p, g_w1);

    // 1. pack conv weight tap K-1
    pack_conv_kernel<<<(DIM * DIM + 255) / 256, 256>>>(conv_w);

    dim3 ggrid(DIM / BN, BATCH / BM);   // (8, 256)

    // 2. x_conv = SiLU(inputs @ w1^T + conv_b)
    gemm_nt_kernel<1><<<ggrid, 256>>>(inputs, w1_p, conv_b, xconv_p, DIM, DIM);

    // 3. z = inputs @ z_w^T
    gemm_nt_kernel<0><<<ggrid, 256>>>(inputs, z_w, nullptr, z_p, HID, DIM);

    // 4. gates + state update + per-head LN
    gate_kernel<<<BATCH, 256>>>(inputs, c, n, m, i_w, i_b, f_w, f_b,
                                o_w, o_b, gn_w, gn_b, out_c, out_n, out_m);

    // 5. out = h_norm @ out_w^T
    gemm_nt_kernel<0><<<ggrid, 256>>>(hnorm_p, out_w, nullptr, out, DIM, HID);
}

// round 4
// speedup vs baseline: 2.2264x; 2.2264x over previous
#include <cuda_runtime.h>
#include <cuda_bf16.h>
#include <cstdint>

// Problem constants (fixed shapes)
#define BATCH 32768
#define DIM   1024
#define NH    8
#define HDIM  128
#define HID   1024
#define KCONV 4
#define EPS_  1e-6f
#define CAP_  15.0f

// ---------------- scratch (static device globals; no allocation) -------------
__device__ float g_xconv[(size_t)BATCH * DIM];   // SiLU(conv gemm), fp32
__device__ float g_z[(size_t)BATCH * DIM];       // z projection, fp32
__device__ __nv_bfloat16 g_in_hi[(size_t)BATCH * DIM];
__device__ __nv_bfloat16 g_in_lo[(size_t)BATCH * DIM];
__device__ __nv_bfloat16 g_hn_hi[(size_t)BATCH * DIM];
__device__ __nv_bfloat16 g_hn_lo[(size_t)BATCH * DIM];
__device__ __nv_bfloat16 g_w1_hi[(size_t)DIM * DIM];
__device__ __nv_bfloat16 g_w1_lo[(size_t)DIM * DIM];
__device__ __nv_bfloat16 g_zw_hi[(size_t)DIM * DIM];
__device__ __nv_bfloat16 g_zw_lo[(size_t)DIM * DIM];
__device__ __nv_bfloat16 g_ow_hi[(size_t)DIM * DIM];
__device__ __nv_bfloat16 g_ow_lo[(size_t)DIM * DIM];

// ---------------- helpers -----------------------------------------------------
__device__ __forceinline__ uint32_t smem_u32(const void* p) {
    uint32_t a;
    asm("{ .reg .u64 t; cvta.to.shared.u64 t, %1; cvt.u32.u64 %0, t; }"
        : "=r"(a) : "l"(p));
    return a;
}

__device__ __forceinline__ void cp_async16(uint32_t dst, const void* src) {
    asm volatile("cp.async.cg.shared.global [%0], [%1], 16;"
                 :: "r"(dst), "l"(src) : "memory");
}
#define CP_COMMIT() asm volatile("cp.async.commit_group;" ::: "memory")
#define CP_WAIT(N)  asm volatile("cp.async.wait_group %0;" :: "n"(N) : "memory")

#define LDSM_X4(r0, r1, r2, r3, addr) \
    asm volatile("ldmatrix.sync.aligned.m8n8.x4.shared.b16 {%0,%1,%2,%3}, [%4];" \
                 : "=r"(r0), "=r"(r1), "=r"(r2), "=r"(r3) : "r"(addr))

#define MMA16816(d, a, b0v, b1v) \
    asm volatile("mma.sync.aligned.m16n8k16.row.col.f32.bf16.bf16.f32 " \
                 "{%0,%1,%2,%3}, {%4,%5,%6,%7}, {%8,%9}, {%0,%1,%2,%3};" \
                 : "+f"((d)[0]), "+f"((d)[1]), "+f"((d)[2]), "+f"((d)[3]) \
                 : "r"((a)[0]), "r"((a)[1]), "r"((a)[2]), "r"((a)[3]), \
                   "r"(b0v), "r"(b1v))

// ---------------- conversion kernels -----------------------------------------
__device__ __forceinline__ void split2(float x, __nv_bfloat16& hi, __nv_bfloat16& lo) {
    hi = __float2bfloat16(x);
    lo = __float2bfloat16(x - __bfloat162float(hi));
}

__global__ __launch_bounds__(256)
void split_kernel(const float* __restrict__ src, __nv_bfloat16* __restrict__ hi,
                  __nv_bfloat16* __restrict__ lo, int n4) {
    int i = blockIdx.x * blockDim.x + threadIdx.x;
    if (i >= n4) return;
    float4 v = ((const float4*)src)[i];
    __nv_bfloat16 h0, h1, h2, h3, l0, l1, l2, l3;
    split2(v.x, h0, l0); split2(v.y, h1, l1);
    split2(v.z, h2, l2); split2(v.w, h3, l3);
    __nv_bfloat162 ha = {h0, h1}, hb = {h2, h3};
    __nv_bfloat162 la = {l0, l1}, lb = {l2, l3};
    uint2 ph, pl;
    ph.x = *(uint32_t*)&ha; ph.y = *(uint32_t*)&hb;
    pl.x = *(uint32_t*)&la; pl.y = *(uint32_t*)&lb;
    ((uint2*)hi)[i] = ph;
    ((uint2*)lo)[i] = pl;
}

__global__ __launch_bounds__(256)
void pack_w1_kernel(const float* __restrict__ conv_w) {
    int idx = blockIdx.x * blockDim.x + threadIdx.x;
    if (idx < DIM * DIM) {
        float x = conv_w[(size_t)idx * KCONV + (KCONV - 1)];
        __nv_bfloat16 h, l;
        split2(x, h, l);
        g_w1_hi[idx] = h;
        g_w1_lo[idx] = l;
    }
}

// ---------------- legacy-MMA GEMM: C[m][n] = sum_k A[m][k]*W[n][k] -----------
// 128x128 tile, BK=32, 256 threads (warps 4x2, each 32x64).
// A,B given as (hi, lo) bf16; computes Ah*Bh + Ah*Bl + Al*Bh into fp32 acc.
#define GK      1024
#define BKC     32
#define NCHUNK  (GK / BKC)          // 32
#define RSB     80                  // padded smem row stride (64B data + 16B pad)
#define TILE_SB (128 * RSB)         // 10240 B per tile
#define STAGE_SB (4 * TILE_SB)      // Ah, Al, Bh, Bl
#define GEMM_SMEM (2 * STAGE_SB)    // 81920 B

template <int ACT>  // 0: none, 1: +bias then SiLU
__global__ __launch_bounds__(256, 2)
void mma_gemm(const __nv_bfloat16* __restrict__ Ah, const __nv_bfloat16* __restrict__ Al,
              const __nv_bfloat16* __restrict__ Bh, const __nv_bfloat16* __restrict__ Bl,
              const float* __restrict__ bias, float* __restrict__ C) {
    extern __shared__ __align__(128) char dsm[];

    const int tid  = threadIdx.x;
    const int wid  = tid >> 5;
    const int lane = tid & 31;
    const int wm   = wid & 3;      // 0..3 -> row block of 32
    const int wn   = wid >> 2;     // 0..1 -> col block of 64
    const int bm = blockIdx.y * 128;
    const int bn = blockIdx.x * 128;

    const uint32_t sbase = smem_u32(dsm);

    const __nv_bfloat16* srcs[4] = {
        Ah + (size_t)bm * GK, Al + (size_t)bm * GK,
        Bh + (size_t)bn * GK, Bl + (size_t)bn * GK };

    // stage loader: 4 tiles of 128 rows x 32 bf16 (64B) each; 16B per cp.async
    auto load_stage = [&](int stage, int k0) {
#pragma unroll
        for (int i = 0; i < 8; i++) {
            int id = tid + i * 256;        // 0..2047
            int t  = id >> 9;              // tile
            int r  = (id >> 2) & 127;      // row
            int cq = id & 3;               // 16B chunk in row
            const void* g = srcs[t] + (size_t)r * GK + k0 + cq * 8;
            uint32_t d = sbase + stage * STAGE_SB + t * TILE_SB + r * RSB + cq * 16;
            cp_async16(d, g);
        }
        CP_COMMIT();
    };

    float acc[2][8][4];
#pragma unroll
    for (int a = 0; a < 2; a++)
#pragma unroll
        for (int b = 0; b < 8; b++)
#pragma unroll
            for (int q = 0; q < 4; q++) acc[a][b][q] = 0.f;

    load_stage(0, 0);

    // fragment address offsets (within a tile)
    const int a_row = wm * 32 + (lane & 7) + ((lane >> 3) & 1) * 8;
    const int a_kof = (lane >> 4) * 8;
    const int b_row = wn * 64 + ((lane >> 4) * 8) + (lane & 7);
    const int b_kof = ((lane >> 3) & 1) * 8;

    for (int ch = 0; ch < NCHUNK; ch++) {
        const int cur = ch & 1;
        if (ch + 1 < NCHUNK) {
            load_stage(cur ^ 1, (ch + 1) * BKC);
            CP_WAIT(1);
        } else {
            CP_WAIT(0);
        }
        __syncthreads();

        const uint32_t st = sbase + cur * STAGE_SB;
        const uint32_t t_ah = st;
        const uint32_t t_al = st + TILE_SB;
        const uint32_t t_bh = st + 2 * TILE_SB;
        const uint32_t t_bl = st + 3 * TILE_SB;

#pragma unroll
        for (int ks = 0; ks < 2; ks++) {
            const int kq = ks * 16;
            uint32_t a1[2][4], a2[2][4], bb[4][4];

            // A_hi frags
#pragma unroll
            for (int mi = 0; mi < 2; mi++) {
                uint32_t ad = t_ah + (a_row + mi * 16) * RSB + (kq + a_kof) * 2;
                LDSM_X4(a1[mi][0], a1[mi][1], a1[mi][2], a1[mi][3], ad);
            }
            // B_hi frags
#pragma unroll
            for (int ni = 0; ni < 4; ni++) {
                uint32_t bd = t_bh + (b_row + ni * 16) * RSB + (kq + b_kof) * 2;
                LDSM_X4(bb[ni][0], bb[ni][1], bb[ni][2], bb[ni][3], bd);
            }
            // hh
#pragma unroll
            for (int mi = 0; mi < 2; mi++)
#pragma unroll
                for (int ni = 0; ni < 4; ni++) {
                    MMA16816(acc[mi][2 * ni],     a1[mi], bb[ni][0], bb[ni][1]);
                    MMA16816(acc[mi][2 * ni + 1], a1[mi], bb[ni][2], bb[ni][3]);
                }
            // A_lo frags, lh
#pragma unroll
            for (int mi = 0; mi < 2; mi++) {
                uint32_t ad = t_al + (a_row + mi * 16) * RSB + (kq + a_kof) * 2;
                LDSM_X4(a2[mi][0], a2[mi][1], a2[mi][2], a2[mi][3], ad);
            }
#pragma unroll
            for (int mi = 0; mi < 2; mi++)
#pragma unroll
                for (int ni = 0; ni < 4; ni++) {
                    MMA16816(acc[mi][2 * ni],     a2[mi], bb[ni][0], bb[ni][1]);
                    MMA16816(acc[mi][2 * ni + 1], a2[mi], bb[ni][2], bb[ni][3]);
                }
            // B_lo frags (overwrite bb), hl
#pragma unroll
            for (int ni = 0; ni < 4; ni++) {
                uint32_t bd = t_bl + (b_row + ni * 16) * RSB + (kq + b_kof) * 2;
                LDSM_X4(bb[ni][0], bb[ni][1], bb[ni][2], bb[ni][3], bd);
            }
#pragma unroll
            for (int mi = 0; mi < 2; mi++)
#pragma unroll
                for (int ni = 0; ni < 4; ni++) {
                    MMA16816(acc[mi][2 * ni],     a1[mi], bb[ni][0], bb[ni][1]);
                    MMA16816(acc[mi][2 * ni + 1], a1[mi], bb[ni][2], bb[ni][3]);
                }
        }
        __syncthreads();
    }

    // epilogue: direct float2 stores
#pragma unroll
    for (int mi = 0; mi < 2; mi++) {
#pragma unroll
        for (int h2 = 0; h2 < 2; h2++) {
            int row = bm + wm * 32 + mi * 16 + (lane >> 2) + h2 * 8;
            float* crow = C + (size_t)row * DIM;
#pragma unroll
            for (int ng = 0; ng < 8; ng++) {
                int col = bn + wn * 64 + ng * 8 + (lane & 3) * 2;
                float x0 = acc[mi][ng][h2 * 2];
                float x1 = acc[mi][ng][h2 * 2 + 1];
                if (ACT == 1) {
                    x0 += bias[col];
                    x1 += bias[col + 1];
                    x0 = x0 / (1.f + __expf(-x0));
                    x1 = x1 / (1.f + __expf(-x1));
                }
                float2 v = {x0, x1};
                *(float2*)(crow + col) = v;
            }
        }
    }
}

// ---------------- gating + per-head layernorm --------------------------------
__device__ __forceinline__ float warp_sum(float v) {
#pragma unroll
    for (int o = 16; o; o >>= 1) v += __shfl_xor_sync(0xffffffffu, v, o);
    return v;
}

__device__ __forceinline__ float softcap(float x) {
    return CAP_ * tanhf(x * (1.0f / CAP_));
}

__global__ __launch_bounds__(256)
void gate_kernel(const float* __restrict__ inputs,
                 const float* __restrict__ c, const float* __restrict__ n,
                 const float* __restrict__ m,
                 const float* __restrict__ i_w, const float* __restrict__ i_b,
                 const float* __restrict__ f_w, const float* __restrict__ f_b,
                 const float* __restrict__ o_w, const float* __restrict__ o_b,
                 const float* __restrict__ gn_w, const float* __restrict__ gn_b,
                 float* __restrict__ out_c, float* __restrict__ out_n,
                 float* __restrict__ out_m) {
    const int b = blockIdx.x;
    const int tid = threadIdx.x;
    const int h = tid >> 5;          // warp == head (NH==8 warps)
    const int lane = tid & 31;

    __shared__ float s_in[DIM];
    __shared__ float s_xc[DIM];

    const float* inrow = inputs + (size_t)b * DIM;
    const float* xcrow = g_xconv + (size_t)b * DIM;
    for (int i = tid; i < DIM; i += 256) {
        s_in[i] = inrow[i];
        s_xc[i] = xcrow[i];
    }
    __syncthreads();

    const float* iw = i_w + h * DIM;
    const float* fw = f_w + h * DIM;
    const float* ow = o_w + h * DIM;
    float di = 0.f, df = 0.f, dq = 0.f;
#pragma unroll 8
    for (int k = lane; k < DIM; k += 32) {
        float xc = s_xc[k];
        float xi = s_in[k];
        di = fmaf(xc, iw[k], di);
        df = fmaf(xc, fw[k], df);
        dq = fmaf(xi, ow[k], dq);
    }
    di = warp_sum(di);
    df = warp_sum(df);
    dq = warp_sum(dq);

    float i_t = softcap(di + i_b[h]);
    float f_t = softcap(df + f_b[h]);
    float o_t = dq + o_b[h];

    float f_log = -log1pf(expf(-f_t));       // log(sigmoid(f_t))
    float mm    = m[(size_t)b * NH + h];
    float m_new = fmaxf(f_log + mm, i_t);
    float i_g   = expf(i_t - m_new);
    float f_g   = expf(f_log + mm - m_new);
    float o_g   = 1.f / (1.f + expf(-o_t));

    const size_t base = (size_t)b * HID + h * HDIM;
    const float* crow = c + base;
    const float* nrow = n + base;
    const float* zrow = g_z + base;

    float hv[4];
    float sum = 0.f, sumsq = 0.f;
#pragma unroll
    for (int jj = 0; jj < 4; jj++) {
        int idx = lane + jj * 32;
        float cn = fmaf(f_g, crow[idx], i_g * zrow[idx]);
        float nn = fmaf(f_g, nrow[idx], i_g);
        out_c[base + idx] = cn;
        out_n[base + idx] = nn;
        float hh = o_g * cn / (nn + EPS_);
        hv[jj] = hh;
        sum += hh;
        sumsq = fmaf(hh, hh, sumsq);
    }
    sum   = warp_sum(sum);
    sumsq = warp_sum(sumsq);
    float mu   = sum * (1.0f / HDIM);
    float var  = sumsq * (1.0f / HDIM) - mu * mu;
    float rstd = rsqrtf(var + EPS_);
#pragma unroll
    for (int jj = 0; jj < 4; jj++) {
        int idx = lane + jj * 32;
        float hn = (hv[jj] - mu) * rstd * gn_w[h * HDIM + idx] + gn_b[h * HDIM + idx];
        __nv_bfloat16 hb, lb;
        split2(hn, hb, lb);
        g_hn_hi[base + idx] = hb;
        g_hn_lo[base + idx] = lb;
    }
    if (lane == 0) out_m[(size_t)b * NH + h] = m_new;
}

// ---------------- launch ------------------------------------------------------
extern "C" void kernel_launch(void* const* d_in, const int* in_sizes, int n_in,
                              void* d_out, int out_size) {
    const float* inputs = (const float*)d_in[0];
    const float* c      = (const float*)d_in[1];
    const float* n      = (const float*)d_in[2];
    const float* m      = (const float*)d_in[3];
    const float* conv_w = (const float*)d_in[4];
    const float* conv_b = (const float*)d_in[5];
    const float* z_w    = (const float*)d_in[6];
    const float* i_w    = (const float*)d_in[7];
    const float* i_b    = (const float*)d_in[8];
    const float* f_w    = (const float*)d_in[9];
    const float* f_b    = (const float*)d_in[10];
    const float* o_w    = (const float*)d_in[11];
    const float* o_b    = (const float*)d_in[12];
    const float* gn_w   = (const float*)d_in[13];
    const float* gn_b   = (const float*)d_in[14];
    const float* out_w  = (const float*)d_in[15];

    float* out   = (float*)d_out;                       // [B, D]
    float* out_c = out   + (size_t)BATCH * DIM;         // [B, NH, H]
    float* out_n = out_c + (size_t)BATCH * DIM;         // [B, NH, H]
    float* out_m = out_n + (size_t)BATCH * DIM;         // [B, NH]

    float *xconv_p, *z_p;
    __nv_bfloat16 *inh_p, *inl_p, *hnh_p, *hnl_p;
    __nv_bfloat16 *w1h_p, *w1l_p, *zwh_p, *zwl_p, *owh_p, *owl_p;
    cudaGetSymbolAddress((void**)&xconv_p, g_xconv);
    cudaGetSymbolAddress((void**)&z_p, g_z);
    cudaGetSymbolAddress((void**)&inh_p, g_in_hi);
    cudaGetSymbolAddress((void**)&inl_p, g_in_lo);
    cudaGetSymbolAddress((void**)&hnh_p, g_hn_hi);
    cudaGetSymbolAddress((void**)&hnl_p, g_hn_lo);
    cudaGetSymbolAddress((void**)&w1h_p, g_w1_hi);
    cudaGetSymbolAddress((void**)&w1l_p, g_w1_lo);
    cudaGetSymbolAddress((void**)&zwh_p, g_zw_hi);
    cudaGetSymbolAddress((void**)&zwl_p, g_zw_lo);
    cudaGetSymbolAddress((void**)&owh_p, g_ow_hi);
    cudaGetSymbolAddress((void**)&owl_p, g_ow_lo);

    cudaFuncSetAttribute(mma_gemm<0>, cudaFuncAttributeMaxDynamicSharedMemorySize, GEMM_SMEM);
    cudaFuncSetAttribute(mma_gemm<1>, cudaFuncAttributeMaxDynamicSharedMemorySize, GEMM_SMEM);

    // conversions
    {
        int n4 = (BATCH * DIM) / 4;
        split_kernel<<<n4 / 256, 256>>>(inputs, inh_p, inl_p, n4);
    }
    pack_w1_kernel<<<(DIM * DIM + 255) / 256, 256>>>(conv_w);
    {
        int n4 = (DIM * DIM) / 4;
        split_kernel<<<n4 / 256, 256>>>(z_w, zwh_p, zwl_p, n4);
        split_kernel<<<n4 / 256, 256>>>(out_w, owh_p, owl_p, n4);
    }

    dim3 ggrid(DIM / 128, BATCH / 128);   // (8, 256)

    // x_conv = SiLU(inputs @ w1^T + conv_b)
    mma_gemm<1><<<ggrid, 256, GEMM_SMEM>>>(inh_p, inl_p, w1h_p, w1l_p, conv_b, xconv_p);
    // z = inputs @ z_w^T
    mma_gemm<0><<<ggrid, 256, GEMM_SMEM>>>(inh_p, inl_p, zwh_p, zwl_p, nullptr, z_p);
    // gates + state update + per-head LN (emits h_norm as bf16 hi/lo)
    gate_kernel<<<BATCH, 256>>>(inputs, c, n, m, i_w, i_b, f_w, f_b,
                                o_w, o_b, gn_w, gn_b, out_c, out_n, out_m);
    // out = h_norm @ out_w^T
    mma_gemm<0><<<ggrid, 256, GEMM_SMEM>>>(hnh_p, hnl_p, owh_p, owl_p, nullptr, out);
}

// round 6
// speedup vs baseline: 2.9066x; 1.3055x over previous
#include <cuda_runtime.h>
#include <cuda_fp16.h>
#include <cstdint>

// Problem constants (fixed shapes)
#define BATCH 32768
#define DIM   1024
#define NH    8
#define HDIM  128
#define HID   1024
#define KCONV 4
#define EPS_  1e-6f
#define CAP_  15.0f

// ---------------- scratch (static device globals; no allocation) -------------
__device__ float g_xconv[(size_t)BATCH * DIM];   // SiLU(conv gemm), fp32
__device__ float g_z[(size_t)BATCH * DIM];       // z projection, fp32
__device__ float g_pre[(size_t)BATCH * NH * 3];  // i_t, f_t, o_t per (b,h)
__device__ __half g_in_hi[(size_t)BATCH * DIM];
__device__ __half g_in_lo[(size_t)BATCH * DIM];
__device__ __half g_hn_hi[(size_t)BATCH * DIM];
__device__ __half g_hn_lo[(size_t)BATCH * DIM];
__device__ __half g_w1[(size_t)DIM * DIM];       // conv tap K-1, fp16
__device__ __half g_zw[(size_t)DIM * DIM];
__device__ __half g_ow[(size_t)DIM * DIM];

// ---------------- helpers -----------------------------------------------------
__device__ __forceinline__ uint32_t smem_u32(const void* p) {
    uint32_t a;
    asm("{ .reg .u64 t; cvta.to.shared.u64 t, %1; cvt.u32.u64 %0, t; }"
        : "=r"(a) : "l"(p));
    return a;
}

__device__ __forceinline__ void cp_async16(uint32_t dst, const void* src) {
    asm volatile("cp.async.cg.shared.global [%0], [%1], 16;"
                 :: "r"(dst), "l"(src) : "memory");
}
#define CP_COMMIT() asm volatile("cp.async.commit_group;" ::: "memory")
#define CP_WAIT(N)  asm volatile("cp.async.wait_group %0;" :: "n"(N) : "memory")

#define LDSM_X4(r0, r1, r2, r3, addr) \
    asm volatile("ldmatrix.sync.aligned.m8n8.x4.shared.b16 {%0,%1,%2,%3}, [%4];" \
                 : "=r"(r0), "=r"(r1), "=r"(r2), "=r"(r3) : "r"(addr))

#define MMA16816(d, a, b0v, b1v) \
    asm volatile("mma.sync.aligned.m16n8k16.row.col.f32.f16.f16.f32 " \
                 "{%0,%1,%2,%3}, {%4,%5,%6,%7}, {%8,%9}, {%0,%1,%2,%3};" \
                 : "+f"((d)[0]), "+f"((d)[1]), "+f"((d)[2]), "+f"((d)[3]) \
                 : "r"((a)[0]), "r"((a)[1]), "r"((a)[2]), "r"((a)[3]), \
                   "r"(b0v), "r"(b1v))

__device__ __forceinline__ void split2h(float x, __half& hi, __half& lo) {
    hi = __float2half(x);
    lo = __float2half(x - __half2float(hi));
}

// ---------------- conversion kernels -----------------------------------------
// fp32 -> fp16 hi/lo limbs (for activation operands)
__global__ __launch_bounds__(256)
void split_kernel(const float* __restrict__ src, __half* __restrict__ hi,
                  __half* __restrict__ lo, int n4) {
    int i = blockIdx.x * blockDim.x + threadIdx.x;
    if (i >= n4) return;
    float4 v = ((const float4*)src)[i];
    __half h0, h1, h2, h3, l0, l1, l2, l3;
    split2h(v.x, h0, l0); split2h(v.y, h1, l1);
    split2h(v.z, h2, l2); split2h(v.w, h3, l3);
    __half2 ha = {h0, h1}, hb = {h2, h3};
    __half2 la = {l0, l1}, lb = {l2, l3};
    uint2 ph, pl;
    ph.x = *(uint32_t*)&ha; ph.y = *(uint32_t*)&hb;
    pl.x = *(uint32_t*)&la; pl.y = *(uint32_t*)&lb;
    ((uint2*)hi)[i] = ph;
    ((uint2*)lo)[i] = pl;
}

// fp32 -> single fp16 (weight operands)
__global__ __launch_bounds__(256)
void cvt_h_kernel(const float* __restrict__ src, __half* __restrict__ dst, int n4) {
    int i = blockIdx.x * blockDim.x + threadIdx.x;
    if (i >= n4) return;
    float4 v = ((const float4*)src)[i];
    __half2 a = {__float2half(v.x), __float2half(v.y)};
    __half2 b = {__float2half(v.z), __float2half(v.w)};
    uint2 p = {*(uint32_t*)&a, *(uint32_t*)&b};
    ((uint2*)dst)[i] = p;
}

// pack conv tap K-1 -> fp16
__global__ __launch_bounds__(256)
void pack_w1_kernel(const float* __restrict__ conv_w) {
    int idx = blockIdx.x * blockDim.x + threadIdx.x;
    if (idx < DIM * DIM)
        g_w1[idx] = __float2half(conv_w[(size_t)idx * KCONV + (KCONV - 1)]);
}

// ---------------- fp16-limb MMA GEMM: C[m][n] = sum_k A[m][k]*W[n][k] --------
// 128x128 tile, BK=32, 256 threads (warps 4x2, each 32x64).
// A as (hi, lo) fp16 limbs, B single fp16. C = Ah*B + Al*B (2 passes).
#define GK      1024
#define BKC     32
#define NCHUNK  (GK / BKC)          // 32
#define RSB     80                  // padded smem row stride (64B data + 16B pad)
#define TILE_SB (128 * RSB)         // 10240 B per tile
#define STAGE_SB (3 * TILE_SB)      // Ah, Al, B
#define GEMM_SMEM (2 * STAGE_SB)    // 61440 B

template <int ACT>  // 0: none, 1: +bias then SiLU
__global__ __launch_bounds__(256, 2)
void mma_gemm(const __half* __restrict__ Ah, const __half* __restrict__ Al,
              const __half* __restrict__ B,
              const float* __restrict__ bias, float* __restrict__ C) {
    extern __shared__ __align__(128) char dsm[];

    const int tid  = threadIdx.x;
    const int wid  = tid >> 5;
    const int lane = tid & 31;
    const int wm   = wid & 3;      // 0..3 -> row block of 32
    const int wn   = wid >> 2;     // 0..1 -> col block of 64
    const int bm = blockIdx.y * 128;
    const int bn = blockIdx.x * 128;

    const uint32_t sbase = smem_u32(dsm);

    const __half* srcs[3] = {
        Ah + (size_t)bm * GK, Al + (size_t)bm * GK, B + (size_t)bn * GK };

    // stage loader: 3 tiles of 128 rows x 32 fp16 (64B); 16B per cp.async
    auto load_stage = [&](int stage, int k0) {
#pragma unroll
        for (int i = 0; i < 6; i++) {
            int id = tid + i * 256;        // 0..1535
            int t  = id >> 9;              // tile
            int r  = (id >> 2) & 127;      // row
            int cq = id & 3;               // 16B chunk in row
            const void* g = srcs[t] + (size_t)r * GK + k0 + cq * 8;
            uint32_t d = sbase + stage * STAGE_SB + t * TILE_SB + r * RSB + cq * 16;
            cp_async16(d, g);
        }
        CP_COMMIT();
    };

    float acc[2][8][4];
#pragma unroll
    for (int a = 0; a < 2; a++)
#pragma unroll
        for (int b = 0; b < 8; b++)
#pragma unroll
            for (int q = 0; q < 4; q++) acc[a][b][q] = 0.f;

    load_stage(0, 0);

    // fragment address offsets (within a tile)
    const int a_row = wm * 32 + (lane & 7) + ((lane >> 3) & 1) * 8;
    const int a_kof = (lane >> 4) * 8;
    const int b_row = wn * 64 + ((lane >> 4) * 8) + (lane & 7);
    const int b_kof = ((lane >> 3) & 1) * 8;

    for (int ch = 0; ch < NCHUNK; ch++) {
        const int cur = ch & 1;
        if (ch + 1 < NCHUNK) {
            load_stage(cur ^ 1, (ch + 1) * BKC);
            CP_WAIT(1);
        } else {
            CP_WAIT(0);
        }
        __syncthreads();

        const uint32_t st = sbase + cur * STAGE_SB;
        const uint32_t t_ah = st;
        const uint32_t t_al = st + TILE_SB;
        const uint32_t t_b  = st + 2 * TILE_SB;

#pragma unroll
        for (int ks = 0; ks < 2; ks++) {
            const int kq = ks * 16;
            uint32_t a1[2][4], a2[2][4], bb[4][4];

#pragma unroll
            for (int mi = 0; mi < 2; mi++) {
                uint32_t ad = t_ah + (a_row + mi * 16) * RSB + (kq + a_kof) * 2;
                LDSM_X4(a1[mi][0], a1[mi][1], a1[mi][2], a1[mi][3], ad);
            }
#pragma unroll
            for (int ni = 0; ni < 4; ni++) {
                uint32_t bd = t_b + (b_row + ni * 16) * RSB + (kq + b_kof) * 2;
                LDSM_X4(bb[ni][0], bb[ni][1], bb[ni][2], bb[ni][3], bd);
            }
            // hi pass
#pragma unroll
            for (int mi = 0; mi < 2; mi++)
#pragma unroll
                for (int ni = 0; ni < 4; ni++) {
                    MMA16816(acc[mi][2 * ni],     a1[mi], bb[ni][0], bb[ni][1]);
                    MMA16816(acc[mi][2 * ni + 1], a1[mi], bb[ni][2], bb[ni][3]);
                }
            // lo pass
#pragma unroll
            for (int mi = 0; mi < 2; mi++) {
                uint32_t ad = t_al + (a_row + mi * 16) * RSB + (kq + a_kof) * 2;
                LDSM_X4(a2[mi][0], a2[mi][1], a2[mi][2], a2[mi][3], ad);
            }
#pragma unroll
            for (int mi = 0; mi < 2; mi++)
#pragma unroll
                for (int ni = 0; ni < 4; ni++) {
                    MMA16816(acc[mi][2 * ni],     a2[mi], bb[ni][0], bb[ni][1]);
                    MMA16816(acc[mi][2 * ni + 1], a2[mi], bb[ni][2], bb[ni][3]);
                }
        }
        __syncthreads();
    }

    // epilogue: direct float2 stores
#pragma unroll
    for (int mi = 0; mi < 2; mi++) {
#pragma unroll
        for (int h2 = 0; h2 < 2; h2++) {
            int row = bm + wm * 32 + mi * 16 + (lane >> 2) + h2 * 8;
            float* crow = C + (size_t)row * DIM;
#pragma unroll
            for (int ng = 0; ng < 8; ng++) {
                int col = bn + wn * 64 + ng * 8 + (lane & 3) * 2;
                float x0 = acc[mi][ng][h2 * 2];
                float x1 = acc[mi][ng][h2 * 2 + 1];
                if (ACT == 1) {
                    x0 += bias[col];
                    x1 += bias[col + 1];
                    x0 = x0 / (1.f + __expf(-x0));
                    x1 = x1 / (1.f + __expf(-x1));
                }
                float2 v = {x0, x1};
                *(float2*)(crow + col) = v;
            }
        }
    }
}

// ---------------- gate pre-activations (weights cached in smem) --------------
__device__ __forceinline__ float warp_sum(float v) {
#pragma unroll
    for (int o = 16; o; o >>= 1) v += __shfl_xor_sync(0xffffffffu, v, o);
    return v;
}

__device__ __forceinline__ float softcap(float x) {
    return CAP_ * tanhf(x * (1.0f / CAP_));
}

#define PRE_ROWS 32
#define PRE_SMEM ((3 * NH * DIM + 2 * DIM) * 4)   // 106496 B

__global__ __launch_bounds__(256)
void preact_kernel(const float* __restrict__ inputs,
                   const float* __restrict__ i_w, const float* __restrict__ i_b,
                   const float* __restrict__ f_w, const float* __restrict__ f_b,
                   const float* __restrict__ o_w, const float* __restrict__ o_b) {
    extern __shared__ __align__(16) float sw[];
    float* s_iw = sw;                     // [NH*DIM]
    float* s_fw = s_iw + NH * DIM;
    float* s_ow = s_fw + NH * DIM;
    float* s_xc = s_ow + NH * DIM;        // [DIM]
    float* s_xi = s_xc + DIM;             // [DIM]

    const int tid = threadIdx.x;
    const int h = tid >> 5;
    const int lane = tid & 31;

    // cache all gate weights (96 KB) once per block
#pragma unroll
    for (int i = 0; i < 8; i++) {
        int idx = tid + i * 256;          // over NH*DIM/4 = 2048 float4
        ((float4*)s_iw)[idx] = ((const float4*)i_w)[idx];
        ((float4*)s_fw)[idx] = ((const float4*)f_w)[idx];
        ((float4*)s_ow)[idx] = ((const float4*)o_w)[idx];
    }
    __syncthreads();

    const float ib = i_b[h], fb = f_b[h], ob = o_b[h];
    const int row0 = blockIdx.x * PRE_ROWS;

    for (int r = 0; r < PRE_ROWS; r++) {
        const int row = row0 + r;
        // stage the two activation rows
#pragma unroll
        for (int i = 0; i < 2; i++) {
            int idx = tid + i * 256;      // over DIM/4 = 256 float4 each
            ((float4*)s_xc)[idx & 255] = (i == 0)
                ? ((const float4*)(g_xconv + (size_t)row * DIM))[idx]
                : ((float4*)s_xc)[idx & 255];
            // note: handled below properly
        }
        // simple cooperative loads (256 float4 per row per array)
        {
            int idx = tid;
            ((float4*)s_xc)[idx] = ((const float4*)(g_xconv + (size_t)row * DIM))[idx];
            ((float4*)s_xi)[idx] = ((const float4*)(inputs + (size_t)row * DIM))[idx];
        }
        __syncthreads();

        float di = 0.f, df = 0.f, dq = 0.f;
        const float4* xc4 = (const float4*)s_xc;
        const float4* xi4 = (const float4*)s_xi;
        const float4* iw4 = (const float4*)(s_iw + h * DIM);
        const float4* fw4 = (const float4*)(s_fw + h * DIM);
        const float4* ow4 = (const float4*)(s_ow + h * DIM);
#pragma unroll
        for (int kk = 0; kk < 8; kk++) {
            int k4 = kk * 32 + lane;
            float4 xc = xc4[k4], xi = xi4[k4];
            float4 iw = iw4[k4], fw = fw4[k4], ow = ow4[k4];
            di = fmaf(xc.x, iw.x, di); di = fmaf(xc.y, iw.y, di);
            di = fmaf(xc.z, iw.z, di); di = fmaf(xc.w, iw.w, di);
            df = fmaf(xc.x, fw.x, df); df = fmaf(xc.y, fw.y, df);
            df = fmaf(xc.z, fw.z, df); df = fmaf(xc.w, fw.w, df);
            dq = fmaf(xi.x, ow.x, dq); dq = fmaf(xi.y, ow.y, dq);
            dq = fmaf(xi.z, ow.z, dq); dq = fmaf(xi.w, ow.w, dq);
        }
        di = warp_sum(di);
        df = warp_sum(df);
        dq = warp_sum(dq);
        if (lane == 0) {
            size_t p = ((size_t)row * NH + h) * 3;
            g_pre[p + 0] = softcap(di + ib);
            g_pre[p + 1] = softcap(df + fb);
            g_pre[p + 2] = dq + ob;
        }
        __syncthreads();
    }
}

// ---------------- elementwise gating + per-head layernorm --------------------
__global__ __launch_bounds__(256)
void gate_kernel(const float* __restrict__ c, const float* __restrict__ n,
                 const float* __restrict__ m,
                 const float* __restrict__ gn_w, const float* __restrict__ gn_b,
                 float* __restrict__ out_c, float* __restrict__ out_n,
                 float* __restrict__ out_m) {
    const int b = blockIdx.x;
    const int tid = threadIdx.x;
    const int h = tid >> 5;          // warp == head (NH==8 warps)
    const int lane = tid & 31;

    const size_t p = ((size_t)b * NH + h) * 3;
    const float i_t = g_pre[p + 0];
    const float f_t = g_pre[p + 1];
    const float o_t = g_pre[p + 2];

    float f_log = -log1pf(expf(-f_t));       // log(sigmoid(f_t))
    float mm    = m[(size_t)b * NH + h];
    float m_new = fmaxf(f_log + mm, i_t);
    float i_g   = expf(i_t - m_new);
    float f_g   = expf(f_log + mm - m_new);
    float o_g   = 1.f / (1.f + expf(-o_t));

    const size_t base = (size_t)b * HID + h * HDIM;
    const float* crow = c + base;
    const float* nrow = n + base;
    const float* zrow = g_z + base;

    float hv[4];
    float sum = 0.f, sumsq = 0.f;
#pragma unroll
    for (int jj = 0; jj < 4; jj++) {
        int idx = lane + jj * 32;
        float cn = fmaf(f_g, crow[idx], i_g * zrow[idx]);
        float nn = fmaf(f_g, nrow[idx], i_g);
        out_c[base + idx] = cn;
        out_n[base + idx] = nn;
        float hh = o_g * cn / (nn + EPS_);
        hv[jj] = hh;
        sum += hh;
        sumsq = fmaf(hh, hh, sumsq);
    }
    sum   = warp_sum(sum);
    sumsq = warp_sum(sumsq);
    float mu   = sum * (1.0f / HDIM);
    float var  = sumsq * (1.0f / HDIM) - mu * mu;
    float rstd = rsqrtf(var + EPS_);
#pragma unroll
    for (int jj = 0; jj < 4; jj++) {
        int idx = lane + jj * 32;
        float hn = (hv[jj] - mu) * rstd * gn_w[h * HDIM + idx] + gn_b[h * HDIM + idx];
        __half hb, lb;
        split2h(hn, hb, lb);
        g_hn_hi[base + idx] = hb;
        g_hn_lo[base + idx] = lb;
    }
    if (lane == 0) out_m[(size_t)b * NH + h] = m_new;
}

// ---------------- launch ------------------------------------------------------
extern "C" void kernel_launch(void* const* d_in, const int* in_sizes, int n_in,
                              void* d_out, int out_size) {
    const float* inputs = (const float*)d_in[0];
    const float* c      = (const float*)d_in[1];
    const float* n      = (const float*)d_in[2];
    const float* m      = (const float*)d_in[3];
    const float* conv_w = (const float*)d_in[4];
    const float* conv_b = (const float*)d_in[5];
    const float* z_w    = (const float*)d_in[6];
    const float* i_w    = (const float*)d_in[7];
    const float* i_b    = (const float*)d_in[8];
    const float* f_w    = (const float*)d_in[9];
    const float* f_b    = (const float*)d_in[10];
    const float* o_w    = (const float*)d_in[11];
    const float* o_b    = (const float*)d_in[12];
    const float* gn_w   = (const float*)d_in[13];
    const float* gn_b   = (const float*)d_in[14];
    const float* out_w  = (const float*)d_in[15];

    float* out   = (float*)d_out;                       // [B, D]
    float* out_c = out   + (size_t)BATCH * DIM;         // [B, NH, H]
    float* out_n = out_c + (size_t)BATCH * DIM;         // [B, NH, H]
    float* out_m = out_n + (size_t)BATCH * DIM;         // [B, NH]

    float *xconv_p, *z_p;
    __half *inh_p, *inl_p, *hnh_p, *hnl_p, *w1_p, *zw_p, *ow_p;
    cudaGetSymbolAddress((void**)&xconv_p, g_xconv);
    cudaGetSymbolAddress((void**)&z_p, g_z);
    cudaGetSymbolAddress((void**)&inh_p, g_in_hi);
    cudaGetSymbolAddress((void**)&inl_p, g_in_lo);
    cudaGetSymbolAddress((void**)&hnh_p, g_hn_hi);
    cudaGetSymbolAddress((void**)&hnl_p, g_hn_lo);
    cudaGetSymbolAddress((void**)&w1_p, g_w1);
    cudaGetSymbolAddress((void**)&zw_p, g_zw);
    cudaGetSymbolAddress((void**)&ow_p, g_ow);

    cudaFuncSetAttribute(mma_gemm<0>, cudaFuncAttributeMaxDynamicSharedMemorySize, GEMM_SMEM);
    cudaFuncSetAttribute(mma_gemm<1>, cudaFuncAttributeMaxDynamicSharedMemorySize, GEMM_SMEM);
    cudaFuncSetAttribute(preact_kernel, cudaFuncAttributeMaxDynamicSharedMemorySize, PRE_SMEM);

    // conversions
    {
        int n4 = (BATCH * DIM) / 4;
        split_kernel<<<n4 / 256, 256>>>(inputs, inh_p, inl_p, n4);
    }
    pack_w1_kernel<<<(DIM * DIM + 255) / 256, 256>>>(conv_w);
    {
        int n4 = (DIM * DIM) / 4;
        cvt_h_kernel<<<n4 / 256, 256>>>(z_w, zw_p, n4);
        cvt_h_kernel<<<n4 / 256, 256>>>(out_w, ow_p, n4);
    }

    dim3 ggrid(DIM / 128, BATCH / 128);   // (8, 256)

    // x_conv = SiLU(inputs @ w1^T + conv_b)
    mma_gemm<1><<<ggrid, 256, GEMM_SMEM>>>(inh_p, inl_p, w1_p, conv_b, xconv_p);
    // z = inputs @ z_w^T
    mma_gemm<0><<<ggrid, 256, GEMM_SMEM>>>(inh_p, inl_p, zw_p, nullptr, z_p);
    // gate pre-activations (i_t, f_t, o_t)
    preact_kernel<<<BATCH / PRE_ROWS, 256, PRE_SMEM>>>(inputs, i_w, i_b, f_w, f_b, o_w, o_b);
    // elementwise gating + LN (emits h_norm as fp16 hi/lo limbs)
    gate_kernel<<<BATCH, 256>>>(c, n, m, gn_w, gn_b, out_c, out_n, out_m);
    // out = h_norm @ out_w^T
    mma_gemm<0><<<ggrid, 256, GEMM_SMEM>>>(hnh_p, hnl_p, ow_p, nullptr, out);
}

// round 7
// speedup vs baseline: 3.9315x; 1.3526x over previous
#include <cuda_runtime.h>
#include <cuda_fp16.h>
#include <cstdint>

// Problem constants (fixed shapes)
#define BATCH 32768
#define DIM   1024
#define NH    8
#define HDIM  128
#define HID   1024
#define KCONV 4
#define EPS_  1e-6f
#define CAP_  15.0f

// ---------------- scratch (static device globals; no allocation) -------------
__device__ float g_xconv[(size_t)BATCH * DIM];   // SiLU(conv gemm), fp32
__device__ float g_z[(size_t)BATCH * DIM];       // z projection, fp32
__device__ float g_pre[(size_t)BATCH * NH * 3];  // i_t, f_t, o_t per (b,h)
__device__ __half g_in[(size_t)BATCH * DIM];     // inputs, fp16
__device__ __half g_hn[(size_t)BATCH * DIM];     // h_norm, fp16
__device__ __half g_w1[(size_t)DIM * DIM];       // conv tap K-1, fp16
__device__ __half g_zw[(size_t)DIM * DIM];
__device__ __half g_ow[(size_t)DIM * DIM];

// ---------------- helpers -----------------------------------------------------
__device__ __forceinline__ uint32_t smem_u32(const void* p) {
    uint32_t a;
    asm("{ .reg .u64 t; cvta.to.shared.u64 t, %1; cvt.u32.u64 %0, t; }"
        : "=r"(a) : "l"(p));
    return a;
}

__device__ __forceinline__ void cp_async16(uint32_t dst, const void* src) {
    asm volatile("cp.async.cg.shared.global [%0], [%1], 16;"
                 :: "r"(dst), "l"(src) : "memory");
}
#define CP_COMMIT() asm volatile("cp.async.commit_group;" ::: "memory")
#define CP_WAIT(N)  asm volatile("cp.async.wait_group %0;" :: "n"(N) : "memory")

#define LDSM_X4(r0, r1, r2, r3, addr) \
    asm volatile("ldmatrix.sync.aligned.m8n8.x4.shared.b16 {%0,%1,%2,%3}, [%4];" \
                 : "=r"(r0), "=r"(r1), "=r"(r2), "=r"(r3) : "r"(addr))

#define MMA16816(d, a, b0v, b1v) \
    asm volatile("mma.sync.aligned.m16n8k16.row.col.f32.f16.f16.f32 " \
                 "{%0,%1,%2,%3}, {%4,%5,%6,%7}, {%8,%9}, {%0,%1,%2,%3};" \
                 : "+f"((d)[0]), "+f"((d)[1]), "+f"((d)[2]), "+f"((d)[3]) \
                 : "r"((a)[0]), "r"((a)[1]), "r"((a)[2]), "r"((a)[3]), \
                   "r"(b0v), "r"(b1v))

// ---------------- conversion kernels -----------------------------------------
// fp32 -> fp16
__global__ __launch_bounds__(256)
void cvt_h_kernel(const float* __restrict__ src, __half* __restrict__ dst, int n4) {
    int i = blockIdx.x * blockDim.x + threadIdx.x;
    if (i >= n4) return;
    float4 v = ((const float4*)src)[i];
    __half2 a = {__float2half(v.x), __float2half(v.y)};
    __half2 b = {__float2half(v.z), __float2half(v.w)};
    uint2 p = {*(uint32_t*)&a, *(uint32_t*)&b};
    ((uint2*)dst)[i] = p;
}

// pack conv tap K-1 -> fp16
__global__ __launch_bounds__(256)
void pack_w1_kernel(const float* __restrict__ conv_w) {
    int idx = blockIdx.x * blockDim.x + threadIdx.x;
    if (idx < DIM * DIM)
        g_w1[idx] = __float2half(conv_w[(size_t)idx * KCONV + (KCONV - 1)]);
}

// ---------------- fp16 MMA GEMM: C[m][n] = sum_k A[m][k]*W[n][k] -------------
// 128x128 tile, BK=32, 256 threads (warps 4x2, each 32x64). Single fp16 pass.
#define GK      1024
#define BKC     32
#define NCHUNK  (GK / BKC)          // 32
#define RSB     80                  // padded smem row stride (64B data + 16B pad)
#define TILE_SB (128 * RSB)         // 10240 B per tile
#define STAGE_SB (2 * TILE_SB)      // A, B
#define GEMM_SMEM (2 * STAGE_SB)    // 40960 B

template <int ACT>  // 0: none, 1: +bias then SiLU
__global__ __launch_bounds__(256, 2)
void mma_gemm(const __half* __restrict__ A, const __half* __restrict__ B,
              const float* __restrict__ bias, float* __restrict__ C) {
    extern __shared__ __align__(128) char dsm[];

    const int tid  = threadIdx.x;
    const int wid  = tid >> 5;
    const int lane = tid & 31;
    const int wm   = wid & 3;      // 0..3 -> row block of 32
    const int wn   = wid >> 2;     // 0..1 -> col block of 64
    const int bm = blockIdx.y * 128;
    const int bn = blockIdx.x * 128;

    const uint32_t sbase = smem_u32(dsm);

    const __half* srcs[2] = { A + (size_t)bm * GK, B + (size_t)bn * GK };

    // stage loader: 2 tiles of 128 rows x 32 fp16 (64B); 16B per cp.async
    auto load_stage = [&](int stage, int k0) {
#pragma unroll
        for (int i = 0; i < 4; i++) {
            int id = tid + i * 256;        // 0..1023
            int t  = id >> 9;              // tile
            int r  = (id >> 2) & 127;      // row
            int cq = id & 3;               // 16B chunk in row
            const void* g = srcs[t] + (size_t)r * GK + k0 + cq * 8;
            uint32_t d = sbase + stage * STAGE_SB + t * TILE_SB + r * RSB + cq * 16;
            cp_async16(d, g);
        }
        CP_COMMIT();
    };

    float acc[2][8][4];
#pragma unroll
    for (int a = 0; a < 2; a++)
#pragma unroll
        for (int b = 0; b < 8; b++)
#pragma unroll
            for (int q = 0; q < 4; q++) acc[a][b][q] = 0.f;

    load_stage(0, 0);

    // fragment address offsets (within a tile)
    const int a_row = wm * 32 + (lane & 7) + ((lane >> 3) & 1) * 8;
    const int a_kof = (lane >> 4) * 8;
    const int b_row = wn * 64 + ((lane >> 4) * 8) + (lane & 7);
    const int b_kof = ((lane >> 3) & 1) * 8;

    for (int ch = 0; ch < NCHUNK; ch++) {
        const int cur = ch & 1;
        if (ch + 1 < NCHUNK) {
            load_stage(cur ^ 1, (ch + 1) * BKC);
            CP_WAIT(1);
        } else {
            CP_WAIT(0);
        }
        __syncthreads();

        const uint32_t st  = sbase + cur * STAGE_SB;
        const uint32_t t_a = st;
        const uint32_t t_b = st + TILE_SB;

#pragma unroll
        for (int ks = 0; ks < 2; ks++) {
            const int kq = ks * 16;
            uint32_t aa[2][4], bb[4][4];

#pragma unroll
            for (int mi = 0; mi < 2; mi++) {
                uint32_t ad = t_a + (a_row + mi * 16) * RSB + (kq + a_kof) * 2;
                LDSM_X4(aa[mi][0], aa[mi][1], aa[mi][2], aa[mi][3], ad);
            }
#pragma unroll
            for (int ni = 0; ni < 4; ni++) {
                uint32_t bd = t_b + (b_row + ni * 16) * RSB + (kq + b_kof) * 2;
                LDSM_X4(bb[ni][0], bb[ni][1], bb[ni][2], bb[ni][3], bd);
            }
#pragma unroll
            for (int mi = 0; mi < 2; mi++)
#pragma unroll
                for (int ni = 0; ni < 4; ni++) {
                    MMA16816(acc[mi][2 * ni],     aa[mi], bb[ni][0], bb[ni][1]);
                    MMA16816(acc[mi][2 * ni + 1], aa[mi], bb[ni][2], bb[ni][3]);
                }
        }
        __syncthreads();
    }

    // epilogue: direct float2 stores
#pragma unroll
    for (int mi = 0; mi < 2; mi++) {
#pragma unroll
        for (int h2 = 0; h2 < 2; h2++) {
            int row = bm + wm * 32 + mi * 16 + (lane >> 2) + h2 * 8;
            float* crow = C + (size_t)row * DIM;
#pragma unroll
            for (int ng = 0; ng < 8; ng++) {
                int col = bn + wn * 64 + ng * 8 + (lane & 3) * 2;
                float x0 = acc[mi][ng][h2 * 2];
                float x1 = acc[mi][ng][h2 * 2 + 1];
                if (ACT == 1) {
                    x0 += bias[col];
                    x1 += bias[col + 1];
                    x0 = x0 / (1.f + __expf(-x0));
                    x1 = x1 / (1.f + __expf(-x1));
                }
                float2 v = {x0, x1};
                *(float2*)(crow + col) = v;
            }
        }
    }
}

// ---------------- gate pre-activations (weights cached in smem) --------------
__device__ __forceinline__ float warp_sum(float v) {
#pragma unroll
    for (int o = 16; o; o >>= 1) v += __shfl_xor_sync(0xffffffffu, v, o);
    return v;
}

__device__ __forceinline__ float softcap(float x) {
    return CAP_ * tanhf(x * (1.0f / CAP_));
}

#define PRE_ROWS 32
#define PRE_SMEM ((3 * NH * DIM + 2 * DIM) * 4)   // 106496 B

__global__ __launch_bounds__(256)
void preact_kernel(const float* __restrict__ inputs,
                   const float* __restrict__ i_w, const float* __restrict__ i_b,
                   const float* __restrict__ f_w, const float* __restrict__ f_b,
                   const float* __restrict__ o_w, const float* __restrict__ o_b) {
    extern __shared__ __align__(16) float sw[];
    float* s_iw = sw;                     // [NH*DIM]
    float* s_fw = s_iw + NH * DIM;
    float* s_ow = s_fw + NH * DIM;
    float* s_xc = s_ow + NH * DIM;        // [DIM]
    float* s_xi = s_xc + DIM;             // [DIM]

    const int tid = threadIdx.x;
    const int h = tid >> 5;
    const int lane = tid & 31;

    // cache all gate weights (96 KB) once per block
#pragma unroll
    for (int i = 0; i < 8; i++) {
        int idx = tid + i * 256;          // over NH*DIM/4 = 2048 float4
        ((float4*)s_iw)[idx] = ((const float4*)i_w)[idx];
        ((float4*)s_fw)[idx] = ((const float4*)f_w)[idx];
        ((float4*)s_ow)[idx] = ((const float4*)o_w)[idx];
    }
    __syncthreads();

    const float ib = i_b[h], fb = f_b[h], ob = o_b[h];
    const int row0 = blockIdx.x * PRE_ROWS;

    for (int r = 0; r < PRE_ROWS; r++) {
        const int row = row0 + r;
        // cooperative loads (256 float4 per row per array)
        {
            int idx = tid;
            ((float4*)s_xc)[idx] = ((const float4*)(g_xconv + (size_t)row * DIM))[idx];
            ((float4*)s_xi)[idx] = ((const float4*)(inputs + (size_t)row * DIM))[idx];
        }
        __syncthreads();

        float di = 0.f, df = 0.f, dq = 0.f;
        const float4* xc4 = (const float4*)s_xc;
        const float4* xi4 = (const float4*)s_xi;
        const float4* iw4 = (const float4*)(s_iw + h * DIM);
        const float4* fw4 = (const float4*)(s_fw + h * DIM);
        const float4* ow4 = (const float4*)(s_ow + h * DIM);
#pragma unroll
        for (int kk = 0; kk < 8; kk++) {
            int k4 = kk * 32 + lane;
            float4 xc = xc4[k4], xi = xi4[k4];
            float4 iw = iw4[k4], fw = fw4[k4], ow = ow4[k4];
            di = fmaf(xc.x, iw.x, di); di = fmaf(xc.y, iw.y, di);
            di = fmaf(xc.z, iw.z, di); di = fmaf(xc.w, iw.w, di);
            df = fmaf(xc.x, fw.x, df); df = fmaf(xc.y, fw.y, df);
            df = fmaf(xc.z, fw.z, df); df = fmaf(xc.w, fw.w, df);
            dq = fmaf(xi.x, ow.x, dq); dq = fmaf(xi.y, ow.y, dq);
            dq = fmaf(xi.z, ow.z, dq); dq = fmaf(xi.w, ow.w, dq);
        }
        di = warp_sum(di);
        df = warp_sum(df);
        dq = warp_sum(dq);
        if (lane == 0) {
            size_t p = ((size_t)row * NH + h) * 3;
            g_pre[p + 0] = softcap(di + ib);
            g_pre[p + 1] = softcap(df + fb);
            g_pre[p + 2] = dq + ob;
        }
        __syncthreads();
    }
}

// ---------------- elementwise gating + per-head layernorm --------------------
__global__ __launch_bounds__(256)
void gate_kernel(const float* __restrict__ c, const float* __restrict__ n,
                 const float* __restrict__ m,
                 const float* __restrict__ gn_w, const float* __restrict__ gn_b,
                 float* __restrict__ out_c, float* __restrict__ out_n,
                 float* __restrict__ out_m) {
    const int b = blockIdx.x;
    const int tid = threadIdx.x;
    const int h = tid >> 5;          // warp == head (NH==8 warps)
    const int lane = tid & 31;

    const size_t p = ((size_t)b * NH + h) * 3;
    const float i_t = g_pre[p + 0];
    const float f_t = g_pre[p + 1];
    const float o_t = g_pre[p + 2];

    float f_log = -log1pf(expf(-f_t));       // log(sigmoid(f_t))
    float mm    = m[(size_t)b * NH + h];
    float m_new = fmaxf(f_log + mm, i_t);
    float i_g   = expf(i_t - m_new);
    float f_g   = expf(f_log + mm - m_new);
    float o_g   = 1.f / (1.f + expf(-o_t));

    const size_t base = (size_t)b * HID + h * HDIM;
    const float* crow = c + base;
    const float* nrow = n + base;
    const float* zrow = g_z + base;

    float hv[4];
    float sum = 0.f, sumsq = 0.f;
#pragma unroll
    for (int jj = 0; jj < 4; jj++) {
        int idx = lane + jj * 32;
        float cn = fmaf(f_g, crow[idx], i_g * zrow[idx]);
        float nn = fmaf(f_g, nrow[idx], i_g);
        out_c[base + idx] = cn;
        out_n[base + idx] = nn;
        float hh = o_g * cn / (nn + EPS_);
        hv[jj] = hh;
        sum += hh;
        sumsq = fmaf(hh, hh, sumsq);
    }
    sum   = warp_sum(sum);
    sumsq = warp_sum(sumsq);
    float mu   = sum * (1.0f / HDIM);
    float var  = sumsq * (1.0f / HDIM) - mu * mu;
    float rstd = rsqrtf(var + EPS_);
#pragma unroll
    for (int jj = 0; jj < 4; jj++) {
        int idx = lane + jj * 32;
        float hn = (hv[jj] - mu) * rstd * gn_w[h * HDIM + idx] + gn_b[h * HDIM + idx];
        g_hn[base + idx] = __float2half(hn);
    }
    if (lane == 0) out_m[(size_t)b * NH + h] = m_new;
}

// ---------------- launch ------------------------------------------------------
extern "C" void kernel_launch(void* const* d_in, const int* in_sizes, int n_in,
                              void* d_out, int out_size) {
    const float* inputs = (const float*)d_in[0];
    const float* c      = (const float*)d_in[1];
    const float* n      = (const float*)d_in[2];
    const float* m      = (const float*)d_in[3];
    const float* conv_w = (const float*)d_in[4];
    const float* conv_b = (const float*)d_in[5];
    const float* z_w    = (const float*)d_in[6];
    const float* i_w    = (const float*)d_in[7];
    const float* i_b    = (const float*)d_in[8];
    const float* f_w    = (const float*)d_in[9];
    const float* f_b    = (const float*)d_in[10];
    const float* o_w    = (const float*)d_in[11];
    const float* o_b    = (const float*)d_in[12];
    const float* gn_w   = (const float*)d_in[13];
    const float* gn_b   = (const float*)d_in[14];
    const float* out_w  = (const float*)d_in[15];

    float* out   = (float*)d_out;                       // [B, D]
    float* out_c = out   + (size_t)BATCH * DIM;         // [B, NH, H]
    float* out_n = out_c + (size_t)BATCH * DIM;         // [B, NH, H]
    float* out_m = out_n + (size_t)BATCH * DIM;         // [B, NH]

    float *xconv_p, *z_p;
    __half *in_p, *hn_p, *w1_p, *zw_p, *ow_p;
    cudaGetSymbolAddress((void**)&xconv_p, g_xconv);
    cudaGetSymbolAddress((void**)&z_p, g_z);
    cudaGetSymbolAddress((void**)&in_p, g_in);
    cudaGetSymbolAddress((void**)&hn_p, g_hn);
    cudaGetSymbolAddress((void**)&w1_p, g_w1);
    cudaGetSymbolAddress((void**)&zw_p, g_zw);
    cudaGetSymbolAddress((void**)&ow_p, g_ow);

    cudaFuncSetAttribute(mma_gemm<0>, cudaFuncAttributeMaxDynamicSharedMemorySize, GEMM_SMEM);
    cudaFuncSetAttribute(mma_gemm<1>, cudaFuncAttributeMaxDynamicSharedMemorySize, GEMM_SMEM);
    cudaFuncSetAttribute(preact_kernel, cudaFuncAttributeMaxDynamicSharedMemorySize, PRE_SMEM);

    // conversions
    {
        int n4 = (BATCH * DIM) / 4;
        cvt_h_kernel<<<n4 / 256, 256>>>(inputs, in_p, n4);
    }
    pack_w1_kernel<<<(DIM * DIM + 255) / 256, 256>>>(conv_w);
    {
        int n4 = (DIM * DIM) / 4;
        cvt_h_kernel<<<n4 / 256, 256>>>(z_w, zw_p, n4);
        cvt_h_kernel<<<n4 / 256, 256>>>(out_w, ow_p, n4);
    }

    dim3 ggrid(DIM / 128, BATCH / 128);   // (8, 256)

    // x_conv = SiLU(inputs @ w1^T + conv_b)
    mma_gemm<1><<<ggrid, 256, GEMM_SMEM>>>(in_p, w1_p, conv_b, xconv_p);
    // z = inputs @ z_w^T
    mma_gemm<0><<<ggrid, 256, GEMM_SMEM>>>(in_p, zw_p, nullptr, z_p);
    // gate pre-activations (i_t, f_t, o_t)
    preact_kernel<<<BATCH / PRE_ROWS, 256, PRE_SMEM>>>(inputs, i_w, i_b, f_w, f_b, o_w, o_b);
    // elementwise gating + LN (emits h_norm as fp16)
    gate_kernel<<<BATCH, 256>>>(c, n, m, gn_w, gn_b, out_c, out_n, out_m);
    // out = h_norm @ out_w^T
    mma_gemm<0><<<ggrid, 256, GEMM_SMEM>>>(hn_p, ow_p, nullptr, out);
}

// round 8
// speedup vs baseline: 4.2646x; 1.0847x over previous
#include <cuda_runtime.h>
#include <cuda_fp16.h>
#include <cstdint>

// Problem constants (fixed shapes)
#define BATCH 32768
#define DIM   1024
#define NH    8
#define HDIM  128
#define HID   1024
#define KCONV 4
#define EPS_  1e-6f
#define CAP_  15.0f

// ---------------- scratch (static device globals; no allocation) -------------
__device__ __half g_xconv[(size_t)BATCH * DIM];  // SiLU(conv gemm), fp16
__device__ float g_z[(size_t)BATCH * DIM];       // z projection, fp32
__device__ float g_pre[(size_t)BATCH * NH * 3];  // i_t, f_t, o_t per (b,h)
__device__ __half g_in[(size_t)BATCH * DIM];     // inputs, fp16
__device__ __half g_hn[(size_t)BATCH * DIM];     // h_norm, fp16
__device__ __half g_wz[(size_t)2 * DIM * DIM];   // [w1 | z_w] packed, fp16
__device__ __half g_ow[(size_t)DIM * DIM];

// ---------------- helpers -----------------------------------------------------
__device__ __forceinline__ uint32_t smem_u32(const void* p) {
    uint32_t a;
    asm("{ .reg .u64 t; cvta.to.shared.u64 t, %1; cvt.u32.u64 %0, t; }"
        : "=r"(a) : "l"(p));
    return a;
}

__device__ __forceinline__ void cp_async16(uint32_t dst, const void* src) {
    asm volatile("cp.async.cg.shared.global [%0], [%1], 16;"
                 :: "r"(dst), "l"(src) : "memory");
}
#define CP_COMMIT() asm volatile("cp.async.commit_group;" ::: "memory")
#define CP_WAIT(N)  asm volatile("cp.async.wait_group %0;" :: "n"(N) : "memory")

#define LDSM_X4(r0, r1, r2, r3, addr) \
    asm volatile("ldmatrix.sync.aligned.m8n8.x4.shared.b16 {%0,%1,%2,%3}, [%4];" \
                 : "=r"(r0), "=r"(r1), "=r"(r2), "=r"(r3) : "r"(addr))

#define MMA16816(d, a, b0v, b1v) \
    asm volatile("mma.sync.aligned.m16n8k16.row.col.f32.f16.f16.f32 " \
                 "{%0,%1,%2,%3}, {%4,%5,%6,%7}, {%8,%9}, {%0,%1,%2,%3};" \
                 : "+f"((d)[0]), "+f"((d)[1]), "+f"((d)[2]), "+f"((d)[3]) \
                 : "r"((a)[0]), "r"((a)[1]), "r"((a)[2]), "r"((a)[3]), \
                   "r"(b0v), "r"(b1v))

// ---------------- conversion kernels -----------------------------------------
// fp32 -> fp16
__global__ __launch_bounds__(256)
void cvt_h_kernel(const float* __restrict__ src, __half* __restrict__ dst, int n4) {
    int i = blockIdx.x * blockDim.x + threadIdx.x;
    if (i >= n4) return;
    float4 v = ((const float4*)src)[i];
    __half2 a = {__float2half(v.x), __float2half(v.y)};
    __half2 b = {__float2half(v.z), __float2half(v.w)};
    uint2 p = {*(uint32_t*)&a, *(uint32_t*)&b};
    ((uint2*)dst)[i] = p;
}

// pack conv tap K-1 -> fp16 (into first half of g_wz)
__global__ __launch_bounds__(256)
void pack_w1_kernel(const float* __restrict__ conv_w) {
    int idx = blockIdx.x * blockDim.x + threadIdx.x;
    if (idx < DIM * DIM)
        g_wz[idx] = __float2half(conv_w[(size_t)idx * KCONV + (KCONV - 1)]);
}

// ---------------- fp16 MMA GEMM: C[m][n] = sum_k A[m][k]*W[n][k] -------------
// 128x128 tile, BK=32, 256 threads (warps 4x2, each 32x64).
// 3-stage cp.async pipeline, one __syncthreads per chunk.
#define GK      1024
#define BKC     32
#define NCHUNK  (GK / BKC)          // 32
#define NSTAGE  3
#define RSB     80                  // padded smem row stride (64B data + 16B pad)
#define TILE_SB (128 * RSB)         // 10240 B per tile
#define STAGE_SB (2 * TILE_SB)      // A, B
#define GEMM_SMEM (NSTAGE * STAGE_SB) // 61440 B

// EPI: 0 = plain fp32 C store (out GEMM, N=1024)
//      1 = fused input GEMM (N=2048): bn<1024 -> bias+SiLU -> half to Cx;
//                                     bn>=1024 -> fp32 to Cz
template <int EPI>
__global__ __launch_bounds__(256, 2)
void mma_gemm(const __half* __restrict__ A, const __half* __restrict__ B,
              const float* __restrict__ bias, float* __restrict__ C,
              __half* __restrict__ Cx) {
    extern __shared__ __align__(128) char dsm[];

    const int tid  = threadIdx.x;
    const int wid  = tid >> 5;
    const int lane = tid & 31;
    const int wm   = wid & 3;      // 0..3 -> row block of 32
    const int wn   = wid >> 2;     // 0..1 -> col block of 64
    const int bm = blockIdx.y * 128;
    const int bn = blockIdx.x * 128;

    const uint32_t sbase = smem_u32(dsm);

    const __half* srcA = A + (size_t)bm * GK;
    const __half* srcB = B + (size_t)bn * GK;

    // stage loader: 2 tiles of 128 rows x 32 fp16 (64B); 16B per cp.async
    auto load_stage = [&](int stage, int k0) {
#pragma unroll
        for (int i = 0; i < 4; i++) {
            int id = tid + i * 256;        // 0..1023
            int t  = id >> 9;              // tile (0=A, 1=B)
            int r  = (id >> 2) & 127;      // row
            int cq = id & 3;               // 16B chunk in row
            const __half* s = (t == 0) ? srcA : srcB;
            const void* g = s + (size_t)r * GK + k0 + cq * 8;
            uint32_t d = sbase + stage * STAGE_SB + t * TILE_SB + r * RSB + cq * 16;
            cp_async16(d, g);
        }
        CP_COMMIT();
    };

    float acc[2][8][4];
#pragma unroll
    for (int a = 0; a < 2; a++)
#pragma unroll
        for (int b = 0; b < 8; b++)
#pragma unroll
            for (int q = 0; q < 4; q++) acc[a][b][q] = 0.f;

    // prologue: stages 0, 1
    load_stage(0, 0);
    load_stage(1, BKC);

    // fragment address offsets (within a tile)
    const int a_row = wm * 32 + (lane & 7) + ((lane >> 3) & 1) * 8;
    const int a_kof = (lane >> 4) * 8;
    const int b_row = wn * 64 + ((lane >> 4) * 8) + (lane & 7);
    const int b_kof = ((lane >> 3) & 1) * 8;

    int cur = 0, nxt = 2;                       // stage indices mod 3
    for (int ch = 0; ch < NCHUNK; ch++) {
        CP_WAIT(NSTAGE - 2);                    // my group for chunk ch done
        __syncthreads();                        // everyone's done + buf free
        if (ch + 2 < NCHUNK) {
            load_stage(nxt, (ch + 2) * BKC);    // safe: old readers finished
        }

        const uint32_t st  = sbase + cur * STAGE_SB;
        const uint32_t t_a = st;
        const uint32_t t_b = st + TILE_SB;

#pragma unroll
        for (int ks = 0; ks < 2; ks++) {
            const int kq = ks * 16;
            uint32_t aa[2][4], bb[4][4];

#pragma unroll
            for (int mi = 0; mi < 2; mi++) {
                uint32_t ad = t_a + (a_row + mi * 16) * RSB + (kq + a_kof) * 2;
                LDSM_X4(aa[mi][0], aa[mi][1], aa[mi][2], aa[mi][3], ad);
            }
#pragma unroll
            for (int ni = 0; ni < 4; ni++) {
                uint32_t bd = t_b + (b_row + ni * 16) * RSB + (kq + b_kof) * 2;
                LDSM_X4(bb[ni][0], bb[ni][1], bb[ni][2], bb[ni][3], bd);
            }
#pragma unroll
            for (int mi = 0; mi < 2; mi++)
#pragma unroll
                for (int ni = 0; ni < 4; ni++) {
                    MMA16816(acc[mi][2 * ni],     aa[mi], bb[ni][0], bb[ni][1]);
                    MMA16816(acc[mi][2 * ni + 1], aa[mi], bb[ni][2], bb[ni][3]);
                }
        }
        cur = (cur + 1 == NSTAGE) ? 0 : cur + 1;
        nxt = (nxt + 1 == NSTAGE) ? 0 : nxt + 1;
    }

    // epilogue
#pragma unroll
    for (int mi = 0; mi < 2; mi++) {
#pragma unroll
        for (int h2 = 0; h2 < 2; h2++) {
            int row = bm + wm * 32 + mi * 16 + (lane >> 2) + h2 * 8;
#pragma unroll
            for (int ng = 0; ng < 8; ng++) {
                int col = bn + wn * 64 + ng * 8 + (lane & 3) * 2;
                float x0 = acc[mi][ng][h2 * 2];
                float x1 = acc[mi][ng][h2 * 2 + 1];
                if (EPI == 1) {
                    if (bn < DIM) {
                        // x_conv path: bias + SiLU -> fp16
                        x0 += bias[col];
                        x1 += bias[col + 1];
                        x0 = x0 / (1.f + __expf(-x0));
                        x1 = x1 / (1.f + __expf(-x1));
                        __half2 hv = {__float2half(x0), __float2half(x1)};
                        *(__half2*)(Cx + (size_t)row * DIM + col) = hv;
                    } else {
                        float2 v = {x0, x1};
                        *(float2*)(C + (size_t)row * DIM + (col - DIM)) = v;
                    }
                } else {
                    float2 v = {x0, x1};
                    *(float2*)(C + (size_t)row * DIM + col) = v;
                }
            }
        }
    }
}

// ---------------- gate pre-activations (weights cached in smem) --------------
__device__ __forceinline__ float warp_sum(float v) {
#pragma unroll
    for (int o = 16; o; o >>= 1) v += __shfl_xor_sync(0xffffffffu, v, o);
    return v;
}

__device__ __forceinline__ float softcap(float x) {
    return CAP_ * tanhf(x * (1.0f / CAP_));
}

#define PRE_ROWS 32
#define PRE_SMEM ((3 * NH * DIM + 2 * DIM) * 4)   // 106496 B

__global__ __launch_bounds__(256)
void preact_kernel(const float* __restrict__ inputs,
                   const float* __restrict__ i_w, const float* __restrict__ i_b,
                   const float* __restrict__ f_w, const float* __restrict__ f_b,
                   const float* __restrict__ o_w, const float* __restrict__ o_b) {
    extern __shared__ __align__(16) float sw[];
    float* s_iw = sw;                     // [NH*DIM]
    float* s_fw = s_iw + NH * DIM;
    float* s_ow = s_fw + NH * DIM;
    float* s_xc = s_ow + NH * DIM;        // [DIM]
    float* s_xi = s_xc + DIM;             // [DIM]

    const int tid = threadIdx.x;
    const int h = tid >> 5;
    const int lane = tid & 31;

    // cache all gate weights (96 KB) once per block
#pragma unroll
    for (int i = 0; i < 8; i++) {
        int idx = tid + i * 256;          // over NH*DIM/4 = 2048 float4
        ((float4*)s_iw)[idx] = ((const float4*)i_w)[idx];
        ((float4*)s_fw)[idx] = ((const float4*)f_w)[idx];
        ((float4*)s_ow)[idx] = ((const float4*)o_w)[idx];
    }
    __syncthreads();

    const float ib = i_b[h], fb = f_b[h], ob = o_b[h];
    const int row0 = blockIdx.x * PRE_ROWS;

    for (int r = 0; r < PRE_ROWS; r++) {
        const int row = row0 + r;
        // cooperative loads: xconv fp16 (converted to fp32 smem), inputs fp32
        {
            int idx = tid;                // 256 threads
            uint2 hx = ((const uint2*)(g_xconv + (size_t)row * DIM))[idx];
            __half2 h0 = *(__half2*)&hx.x;
            __half2 h1 = *(__half2*)&hx.y;
            float2 f0 = __half22float2(h0);
            float2 f1 = __half22float2(h1);
            float4 xf = {f0.x, f0.y, f1.x, f1.y};
            ((float4*)s_xc)[idx] = xf;
            ((float4*)s_xi)[idx] = ((const float4*)(inputs + (size_t)row * DIM))[idx];
        }
        __syncthreads();

        float di = 0.f, df = 0.f, dq = 0.f;
        const float4* xc4 = (const float4*)s_xc;
        const float4* xi4 = (const float4*)s_xi;
        const float4* iw4 = (const float4*)(s_iw + h * DIM);
        const float4* fw4 = (const float4*)(s_fw + h * DIM);
        const float4* ow4 = (const float4*)(s_ow + h * DIM);
#pragma unroll
        for (int kk = 0; kk < 8; kk++) {
            int k4 = kk * 32 + lane;
            float4 xc = xc4[k4], xi = xi4[k4];
            float4 iw = iw4[k4], fw = fw4[k4], ow = ow4[k4];
            di = fmaf(xc.x, iw.x, di); di = fmaf(xc.y, iw.y, di);
            di = fmaf(xc.z, iw.z, di); di = fmaf(xc.w, iw.w, di);
            df = fmaf(xc.x, fw.x, df); df = fmaf(xc.y, fw.y, df);
            df = fmaf(xc.z, fw.z, df); df = fmaf(xc.w, fw.w, df);
            dq = fmaf(xi.x, ow.x, dq); dq = fmaf(xi.y, ow.y, dq);
            dq = fmaf(xi.z, ow.z, dq); dq = fmaf(xi.w, ow.w, dq);
        }
        di = warp_sum(di);
        df = warp_sum(df);
        dq = warp_sum(dq);
        if (lane == 0) {
            size_t p = ((size_t)row * NH + h) * 3;
            g_pre[p + 0] = softcap(di + ib);
            g_pre[p + 1] = softcap(df + fb);
            g_pre[p + 2] = dq + ob;
        }
        __syncthreads();
    }
}

// ---------------- elementwise gating + per-head layernorm --------------------
__global__ __launch_bounds__(256)
void gate_kernel(const float* __restrict__ c, const float* __restrict__ n,
                 const float* __restrict__ m,
                 const float* __restrict__ gn_w, const float* __restrict__ gn_b,
                 float* __restrict__ out_c, float* __restrict__ out_n,
                 float* __restrict__ out_m) {
    const int b = blockIdx.x;
    const int tid = threadIdx.x;
    const int h = tid >> 5;          // warp == head (NH==8 warps)
    const int lane = tid & 31;

    const size_t p = ((size_t)b * NH + h) * 3;
    const float i_t = g_pre[p + 0];
    const float f_t = g_pre[p + 1];
    const float o_t = g_pre[p + 2];

    float f_log = -log1pf(expf(-f_t));       // log(sigmoid(f_t))
    float mm    = m[(size_t)b * NH + h];
    float m_new = fmaxf(f_log + mm, i_t);
    float i_g   = expf(i_t - m_new);
    float f_g   = expf(f_log + mm - m_new);
    float o_g   = 1.f / (1.f + expf(-o_t));

    const size_t base = (size_t)b * HID + h * HDIM;
    const int e = lane * 4;                  // 4 contiguous elements per lane

    float4 cv = *(const float4*)(c + base + e);
    float4 nv = *(const float4*)(n + base + e);
    float4 zv = *(const float4*)(g_z + base + e);

    float4 cn, nn, hv;
    cn.x = fmaf(f_g, cv.x, i_g * zv.x); nn.x = fmaf(f_g, nv.x, i_g);
    cn.y = fmaf(f_g, cv.y, i_g * zv.y); nn.y = fmaf(f_g, nv.y, i_g);
    cn.z = fmaf(f_g, cv.z, i_g * zv.z); nn.z = fmaf(f_g, nv.z, i_g);
    cn.w = fmaf(f_g, cv.w, i_g * zv.w); nn.w = fmaf(f_g, nv.w, i_g);
    *(float4*)(out_c + base + e) = cn;
    *(float4*)(out_n + base + e) = nn;

    hv.x = o_g * cn.x / (nn.x + EPS_);
    hv.y = o_g * cn.y / (nn.y + EPS_);
    hv.z = o_g * cn.z / (nn.z + EPS_);
    hv.w = o_g * cn.w / (nn.w + EPS_);

    float sum   = hv.x + hv.y + hv.z + hv.w;
    float sumsq = fmaf(hv.x, hv.x, fmaf(hv.y, hv.y, fmaf(hv.z, hv.z, hv.w * hv.w)));
    sum   = warp_sum(sum);
    sumsq = warp_sum(sumsq);
    float mu   = sum * (1.0f / HDIM);
    float var  = sumsq * (1.0f / HDIM) - mu * mu;
    float rstd = rsqrtf(var + EPS_);

    float4 gw = *(const float4*)(gn_w + h * HDIM + e);
    float4 gb = *(const float4*)(gn_b + h * HDIM + e);
    float h0 = (hv.x - mu) * rstd * gw.x + gb.x;
    float h1 = (hv.y - mu) * rstd * gw.y + gb.y;
    float h2 = (hv.z - mu) * rstd * gw.z + gb.z;
    float h3 = (hv.w - mu) * rstd * gw.w + gb.w;
    __half2 p0 = {__float2half(h0), __float2half(h1)};
    __half2 p1 = {__float2half(h2), __float2half(h3)};
    uint2 hp = {*(uint32_t*)&p0, *(uint32_t*)&p1};
    *(uint2*)(g_hn + base + e) = hp;

    if (lane == 0) out_m[(size_t)b * NH + h] = m_new;
}

// ---------------- launch ------------------------------------------------------
extern "C" void kernel_launch(void* const* d_in, const int* in_sizes, int n_in,
                              void* d_out, int out_size) {
    const float* inputs = (const float*)d_in[0];
    const float* c      = (const float*)d_in[1];
    const float* n      = (const float*)d_in[2];
    const float* m      = (const float*)d_in[3];
    const float* conv_w = (const float*)d_in[4];
    const float* conv_b = (const float*)d_in[5];
    const float* z_w    = (const float*)d_in[6];
    const float* i_w    = (const float*)d_in[7];
    const float* i_b    = (const float*)d_in[8];
    const float* f_w    = (const float*)d_in[9];
    const float* f_b    = (const float*)d_in[10];
    const float* o_w    = (const float*)d_in[11];
    const float* o_b    = (const float*)d_in[12];
    const float* gn_w   = (const float*)d_in[13];
    const float* gn_b   = (const float*)d_in[14];
    const float* out_w  = (const float*)d_in[15];

    float* out   = (float*)d_out;                       // [B, D]
    float* out_c = out   + (size_t)BATCH * DIM;         // [B, NH, H]
    float* out_n = out_c + (size_t)BATCH * DIM;         // [B, NH, H]
    float* out_m = out_n + (size_t)BATCH * DIM;         // [B, NH]

    float *z_p;
    __half *xconv_p, *in_p, *hn_p, *wz_p, *ow_p;
    cudaGetSymbolAddress((void**)&xconv_p, g_xconv);
    cudaGetSymbolAddress((void**)&z_p, g_z);
    cudaGetSymbolAddress((void**)&in_p, g_in);
    cudaGetSymbolAddress((void**)&hn_p, g_hn);
    cudaGetSymbolAddress((void**)&wz_p, g_wz);
    cudaGetSymbolAddress((void**)&ow_p, g_ow);

    cudaFuncSetAttribute(mma_gemm<0>, cudaFuncAttributeMaxDynamicSharedMemorySize, GEMM_SMEM);
    cudaFuncSetAttribute(mma_gemm<1>, cudaFuncAttributeMaxDynamicSharedMemorySize, GEMM_SMEM);
    cudaFuncSetAttribute(preact_kernel, cudaFuncAttributeMaxDynamicSharedMemorySize, PRE_SMEM);

    // conversions
    {
        int n4 = (BATCH * DIM) / 4;
        cvt_h_kernel<<<n4 / 256, 256>>>(inputs, in_p, n4);
    }
    pack_w1_kernel<<<(DIM * DIM + 255) / 256, 256>>>(conv_w);
    {
        int n4 = (DIM * DIM) / 4;
        cvt_h_kernel<<<n4 / 256, 256>>>(z_w, wz_p + (size_t)DIM * DIM, n4);
        cvt_h_kernel<<<n4 / 256, 256>>>(out_w, ow_p, n4);
    }

    // fused input GEMM: [x_conv | z] = inputs @ [w1 | z_w]^T   (N = 2048)
    {
        dim3 g(2 * DIM / 128, BATCH / 128);   // (16, 256)
        mma_gemm<1><<<g, 256, GEMM_SMEM>>>(in_p, wz_p, conv_b, z_p, xconv_p);
    }
    // gate pre-activations (i_t, f_t, o_t)
    preact_kernel<<<BATCH / PRE_ROWS, 256, PRE_SMEM>>>(inputs, i_w, i_b, f_w, f_b, o_w, o_b);
    // elementwise gating + LN (emits h_norm as fp16)
    gate_kernel<<<BATCH, 256>>>(c, n, m, gn_w, gn_b, out_c, out_n, out_m);
    // out = h_norm @ out_w^T
    {
        dim3 g(DIM / 128, BATCH / 128);       // (8, 256)
        mma_gemm<0><<<g, 256, GEMM_SMEM>>>(hn_p, ow_p, nullptr, out, nullptr);
    }
}